// round 1
// baseline (speedup 1.0000x reference)
#include <cuda_runtime.h>

// Analytic reduction of the "quantum multi-head attention" reference:
// For each contiguous group of D_K=8 floats (one head):
//   phi_i = x_i + theta_i,  c_i = cos(phi_i)
//   out[j] = prod_{i=0..j} c_i      (j = 1..7)
//   out[0] = prod_{i=1..7} c_i
// Derivation: product state probabilities are independent Bernoulli; the CNOT
// chain permutes basis states so <Z_j> = E[(-1)^{parity set}] = prod of cos(phi_i)
// over the XOR support of the final bit j.

__global__ __launch_bounds__(256)
void quantum_heads_kernel(const float* __restrict__ x,
                          const float* __restrict__ theta,
                          float* __restrict__ out,
                          int ngroups)
{
    int g = blockIdx.x * blockDim.x + threadIdx.x;
    if (g >= ngroups) return;

    // theta: 8 floats, broadcast (L1/L2 cached)
    float t0 = __ldg(theta + 0);
    float t1 = __ldg(theta + 1);
    float t2 = __ldg(theta + 2);
    float t3 = __ldg(theta + 3);
    float t4 = __ldg(theta + 4);
    float t5 = __ldg(theta + 5);
    float t6 = __ldg(theta + 6);
    float t7 = __ldg(theta + 7);

    const float4* xp = reinterpret_cast<const float4*>(x) + (size_t)g * 2;
    float4 a = __ldg(xp + 0);
    float4 b = __ldg(xp + 1);

    float c0 = cosf(a.x + t0);
    float c1 = cosf(a.y + t1);
    float c2 = cosf(a.z + t2);
    float c3 = cosf(a.w + t3);
    float c4 = cosf(b.x + t4);
    float c5 = cosf(b.y + t5);
    float c6 = cosf(b.z + t6);
    float c7 = cosf(b.w + t7);

    // prefix products p_j = c0*...*cj
    float p1 = c0 * c1;
    float p2 = p1 * c2;
    float p3 = p2 * c3;
    float p4 = p3 * c4;
    float p5 = p4 * c5;
    float p6 = p5 * c6;
    float p7 = p6 * c7;
    // out[0] = c1*...*c7 (suffix product, avoid dividing by c0 which may be 0)
    float s = ((c1 * c2) * (c3 * c4)) * ((c5 * c6) * c7);

    float4 o0 = make_float4(s,  p1, p2, p3);
    float4 o1 = make_float4(p4, p5, p6, p7);

    float4* op = reinterpret_cast<float4*>(out) + (size_t)g * 2;
    op[0] = o0;
    op[1] = o1;
}

extern "C" void kernel_launch(void* const* d_in, const int* in_sizes, int n_in,
                              void* d_out, int out_size)
{
    const float* x     = (const float*)d_in[0];
    const float* theta = (const float*)d_in[1];
    float* out         = (float*)d_out;

    int ngroups = in_sizes[0] / 8;   // one group = 8 contiguous floats (one head)
    int threads = 256;
    int blocks  = (ngroups + threads - 1) / threads;
    quantum_heads_kernel<<<blocks, threads>>>(x, theta, out, ngroups);
}